// round 2
// baseline (speedup 1.0000x reference)
#include <cuda_runtime.h>

#define NB 32
#define NC 2
#define NL 262144
#define NT 1024
#define ND 512
#define NHOP 256
#define NF 257
#define PADL 128
#define TT 16
#define AMINF 1e-10f
#define TEN_OVER_LOG2_10 3.0102999566398120f  // 10 / log2(10)

// Pre-packed folded DFT kernels: rows d=0..255, 256 f-columns, stride 256 (float4-aligned)
__device__ float g_krp[256 * 256];
__device__ float g_kip[256 * 256];
__device__ unsigned int g_pmax;

// ---------------------------------------------------------------------------
// Repack k_real/k_imag (row stride 257 -> 256) + reset global max. Runs every
// launch (graph-replayed), fully deterministic.
// ---------------------------------------------------------------------------
__global__ void prep_kernel(const float* __restrict__ kre,
                            const float* __restrict__ kim) {
    int i = blockIdx.x * 256 + threadIdx.x;  // 0..65535
    int d = i >> 8, f = i & 255;
    g_krp[i] = kre[d * NF + f];
    g_kip[i] = kim[d * NF + f];
    if (i == 0) g_pmax = 0u;
}

// ---------------------------------------------------------------------------
// Main folded-DFT GEMM. grid = (NT/TT, NC, NB), block = 256.
// Thread = 4 f-cols x 4 frames register tile; f covered 0..255.
// ---------------------------------------------------------------------------
__global__ __launch_bounds__(256) void spec_main(const float* __restrict__ x,
                                                 const float* __restrict__ kre,
                                                 float* __restrict__ out) {
    __shared__ float ss[256 * TT];  // s[d][t] = x[d]+x[512-d]
    __shared__ float sa[256 * TT];  // a[d][t] = x[d]-x[512-d]
    __shared__ float xmid[TT];      // x[256] per frame
    __shared__ float red[8];

    const int tid = threadIdx.x;
    const int bx = blockIdx.x, c = blockIdx.y, b = blockIdx.z;
    const float* xin = x + (size_t)(b * NC + c) * NL;
    const int tbase = bx * TT;
    const int gbase = tbase * NHOP - PADL;  // padded-signal offset into x

    // Fold directly from global (coalesced forward + backward runs).
    for (int e = tid; e < 256 * TT; e += 256) {
        int d = e & 255;   // d-consecutive within warp -> coalesced LDG
        int t = e >> 8;
        if (d) {
            int g1 = gbase + t * NHOP + d;
            int g2 = gbase + t * NHOP + ND - d;
            float u = (g1 >= 0 && g1 < NL) ? xin[g1] : 0.f;
            float v = (g2 >= 0 && g2 < NL) ? xin[g2] : 0.f;
            ss[d * TT + t] = u + v;
            sa[d * TT + t] = u - v;
        }
    }
    if (tid < TT) {
        int g = gbase + tid * NHOP + NHOP;
        xmid[tid] = (g >= 0 && g < NL) ? xin[g] : 0.f;
    }
    __syncthreads();

    const int fi = tid & 63, ti = tid >> 6;
    const int f0 = fi * 4, tt0 = ti * 4;

    float aR[4][4], aI[4][4];
#pragma unroll
    for (int i = 0; i < 4; i++)
#pragma unroll
        for (int j = 0; j < 4; j++) { aR[i][j] = 0.f; aI[i][j] = 0.f; }

#pragma unroll 4
    for (int d = 1; d < 256; d++) {
        float4 kr = *(const float4*)&g_krp[d * 256 + f0];
        float4 ki = *(const float4*)&g_kip[d * 256 + f0];
        float4 sv = *(const float4*)&ss[d * TT + tt0];  // broadcast LDS.128
        float4 av = *(const float4*)&sa[d * TT + tt0];
        float krr[4] = {kr.x, kr.y, kr.z, kr.w};
        float kii[4] = {ki.x, ki.y, ki.z, ki.w};
        float svv[4] = {sv.x, sv.y, sv.z, sv.w};
        float avv[4] = {av.x, av.y, av.z, av.w};
#pragma unroll
        for (int i = 0; i < 4; i++)
#pragma unroll
            for (int j = 0; j < 4; j++) {
                aR[i][j] = fmaf(svv[j], krr[i], aR[i][j]);
                aI[i][j] = fmaf(avv[j], kii[i], aI[i][j]);
            }
    }

    // d=256 term for re (k_imag[256] ~ 0), then power -> log, track max power.
    float krm[4];
#pragma unroll
    for (int i = 0; i < 4; i++) krm[i] = __ldg(&kre[256 * NF + f0 + i]);

    float pmax = 0.f;
#pragma unroll
    for (int i = 0; i < 4; i++)
#pragma unroll
        for (int j = 0; j < 4; j++) {
            float re = fmaf(xmid[tt0 + j], krm[i], aR[i][j]);
            float im = aI[i][j];
            float p = fmaxf(fmaf(re, re, im * im), AMINF);
            pmax = fmaxf(pmax, p);
            float lp = TEN_OVER_LOG2_10 * __log2f(p);
            int f = f0 + i, t = tbase + tt0 + j;
            out[(((size_t)b * NF + f) * NT + t) * NC + c] = lp;
        }

    // block max -> one atomic (positive floats: uint order == float order)
#pragma unroll
    for (int o = 16; o; o >>= 1)
        pmax = fmaxf(pmax, __shfl_xor_sync(0xFFFFFFFFu, pmax, o));
    if ((tid & 31) == 0) red[tid >> 5] = pmax;
    __syncthreads();
    if (tid == 0) {
        float m = red[0];
#pragma unroll
        for (int w = 1; w < 8; w++) m = fmaxf(m, red[w]);
        atomicMax(&g_pmax, __float_as_uint(m));
    }
}

// ---------------------------------------------------------------------------
// Nyquist column f=256 (k_imag[:,256] ~ 0). grid = (NT/8, NC, NB), block 256.
// One warp per frame, lanes split the d-reduction (coalesced x loads).
// ---------------------------------------------------------------------------
__global__ void spec_nyq(const float* __restrict__ x,
                         const float* __restrict__ kre,
                         float* __restrict__ out) {
    const int tid = threadIdx.x, lane = tid & 31, w = tid >> 5;
    const int c = blockIdx.y, b = blockIdx.z;
    const int t = blockIdx.x * 8 + w;
    const float* xin = x + (size_t)(b * NC + c) * NL;
    const int gb = t * NHOP - PADL;
    float re = 0.f;
#pragma unroll 4
    for (int d = lane; d < ND; d += 32) {
        int g = gb + d;
        float xv = (g >= 0 && g < NL) ? xin[g] : 0.f;
        re = fmaf(xv, __ldg(&kre[d * NF + 256]), re);
    }
#pragma unroll
    for (int o = 16; o; o >>= 1) re += __shfl_xor_sync(0xFFFFFFFFu, re, o);
    __shared__ float pm[8];
    if (lane == 0) {
        float p = fmaxf(re * re, AMINF);
        out[(((size_t)b * NF + 256) * NT + t) * NC + c] =
            TEN_OVER_LOG2_10 * __log2f(p);
        pm[w] = p;
    }
    __syncthreads();
    if (tid == 0) {
        float m = pm[0];
#pragma unroll
        for (int i = 1; i < 8; i++) m = fmaxf(m, pm[i]);
        atomicMax(&g_pmax, __float_as_uint(m));
    }
}

// ---------------------------------------------------------------------------
// Finalize: subtract global max (in log domain) and clamp. float4 elementwise.
// ---------------------------------------------------------------------------
__global__ void spec_fin(float* __restrict__ out, int n4) {
    int i = blockIdx.x * 256 + threadIdx.x;
    if (i >= n4) return;
    float lmax =
        TEN_OVER_LOG2_10 * __log2f(fmaxf(__uint_as_float(g_pmax), AMINF));
    float4 v = ((float4*)out)[i];
    v.x = fmaxf(v.x - lmax, -80.f);
    v.y = fmaxf(v.y - lmax, -80.f);
    v.z = fmaxf(v.z - lmax, -80.f);
    v.w = fmaxf(v.w - lmax, -80.f);
    ((float4*)out)[i] = v;
}

extern "C" void kernel_launch(void* const* d_in, const int* in_sizes, int n_in,
                              void* d_out, int out_size) {
    const float* x = (const float*)d_in[0];
    const float* kre = (const float*)d_in[1];
    const float* kim = (const float*)d_in[2];
    float* out = (float*)d_out;

    prep_kernel<<<256, 256>>>(kre, kim);

    dim3 gmain(NT / TT, NC, NB);
    spec_main<<<gmain, 256>>>(x, kre, out);

    dim3 gnyq(NT / 8, NC, NB);
    spec_nyq<<<gnyq, 256>>>(x, kre, out);

    int n4 = out_size / 4;
    spec_fin<<<(n4 + 255) / 256, 256>>>(out, n4);
}

// round 3
// speedup vs baseline: 1.0065x; 1.0065x over previous
#include <cuda_runtime.h>

#define NB 32
#define NC 2
#define NL 262144
#define NT 1024
#define ND 512
#define NHOP 256
#define NF 257
#define PADL 128
#define TT 16
#define AMINF 1e-10f
#define TEN_OVER_LOG2_10 3.0102999566398120f  // 10 / log2(10)

typedef unsigned long long u64;

// Pre-packed folded DFT kernels: rows d=0..255, 256 f-cols, stride 256 (16B aligned)
__device__ float g_krp[256 * 256];
__device__ float g_kip[256 * 256];
__device__ unsigned int g_pmax;

#define PACK2(dst, v) \
    asm("mov.b64 %0, {%1, %1};" : "=l"(dst) : "r"(__float_as_uint(v)))
#define FMA2(acc, ka, sb) \
    asm("fma.rn.f32x2 %0, %1, %2, %0;" : "+l"(acc) : "l"(ka), "l"(sb))
#define UNPACK2(lo, hi, v) \
    asm("mov.b64 {%0, %1}, %2;" : "=r"(lo), "=r"(hi) : "l"(v))

// ---------------------------------------------------------------------------
__global__ void prep_kernel(const float* __restrict__ kre,
                            const float* __restrict__ kim) {
    int i = blockIdx.x * 256 + threadIdx.x;  // 0..65535
    int d = i >> 8, f = i & 255;
    g_krp[i] = kre[d * NF + f];
    g_kip[i] = kim[d * NF + f];
    if (i == 0) g_pmax = 0u;
}

// ---------------------------------------------------------------------------
// Main folded-DFT GEMM with packed FFMA2. grid = (NT/TT, NC, NB), block 256.
// Thread tile: 4 f (as 2 f32x2 pairs) x 4 frames, re+im.
// ---------------------------------------------------------------------------
__global__ __launch_bounds__(256) void spec_main(const float* __restrict__ x,
                                                 const float* __restrict__ kre,
                                                 float* __restrict__ out) {
    __shared__ float ss[256 * TT];  // s[d][t] = x[d]+x[512-d]
    __shared__ float sa[256 * TT];  // a[d][t] = x[d]-x[512-d]
    __shared__ float xmid[TT];      // x[256] per frame
    __shared__ float red[8];

    const int tid = threadIdx.x;
    const int bx = blockIdx.x, c = blockIdx.y, b = blockIdx.z;
    const float* xin = x + (size_t)(b * NC + c) * NL;
    const int tbase = bx * TT;
    const int gbase = tbase * NHOP - PADL;

    for (int e = tid; e < 256 * TT; e += 256) {
        int d = e & 255;
        int t = e >> 8;
        if (d) {
            int g1 = gbase + t * NHOP + d;
            int g2 = gbase + t * NHOP + ND - d;
            float u = (g1 >= 0 && g1 < NL) ? xin[g1] : 0.f;
            float v = (g2 >= 0 && g2 < NL) ? xin[g2] : 0.f;
            ss[d * TT + t] = u + v;
            sa[d * TT + t] = u - v;
        }
    }
    if (tid < TT) {
        int g = gbase + tid * NHOP + NHOP;
        xmid[tid] = (g >= 0 && g < NL) ? xin[g] : 0.f;
    }
    __syncthreads();

    const int fi = tid & 63, ti = tid >> 6;
    const int f0 = fi * 4, tt0 = ti * 4;

    u64 aR[2][4], aI[2][4];
#pragma unroll
    for (int p = 0; p < 2; p++)
#pragma unroll
        for (int j = 0; j < 4; j++) { aR[p][j] = 0ull; aI[p][j] = 0ull; }

#pragma unroll 2
    for (int d = 1; d < 256; d++) {
        // k pairs: (k_f0,k_f0+1), (k_f0+2,k_f0+3) directly from float4 layout
        ulonglong2 kr2 = *(const ulonglong2*)&g_krp[d * 256 + f0];
        ulonglong2 ki2 = *(const ulonglong2*)&g_kip[d * 256 + f0];
        float4 sv = *(const float4*)&ss[d * TT + tt0];
        float4 av = *(const float4*)&sa[d * TT + tt0];
        u64 s2[4], a2[4];
        PACK2(s2[0], sv.x); PACK2(s2[1], sv.y);
        PACK2(s2[2], sv.z); PACK2(s2[3], sv.w);
        PACK2(a2[0], av.x); PACK2(a2[1], av.y);
        PACK2(a2[2], av.z); PACK2(a2[3], av.w);
#pragma unroll
        for (int j = 0; j < 4; j++) {
            FMA2(aR[0][j], kr2.x, s2[j]);
            FMA2(aR[1][j], kr2.y, s2[j]);
            FMA2(aI[0][j], ki2.x, a2[j]);
            FMA2(aI[1][j], ki2.y, a2[j]);
        }
    }

    // d=256 re term (k_imag[256] ~ 0), power -> log, track max power.
    float krm[4];
#pragma unroll
    for (int i = 0; i < 4; i++) krm[i] = __ldg(&kre[256 * NF + f0 + i]);

    float pmax = 0.f;
#pragma unroll
    for (int p = 0; p < 2; p++)
#pragma unroll
        for (int j = 0; j < 4; j++) {
            unsigned rlo_u, rhi_u, ilo_u, ihi_u;
            UNPACK2(rlo_u, rhi_u, aR[p][j]);
            UNPACK2(ilo_u, ihi_u, aI[p][j]);
            float xm = xmid[tt0 + j];
            int t = tbase + tt0 + j;
#pragma unroll
            for (int h = 0; h < 2; h++) {
                int fofs = 2 * p + h;
                float re = fmaf(xm, krm[fofs],
                                __uint_as_float(h ? rhi_u : rlo_u));
                float im = __uint_as_float(h ? ihi_u : ilo_u);
                float pw = fmaxf(fmaf(re, re, im * im), AMINF);
                pmax = fmaxf(pmax, pw);
                float lp = TEN_OVER_LOG2_10 * __log2f(pw);
                int f = f0 + fofs;
                out[(((size_t)b * NF + f) * NT + t) * NC + c] = lp;
            }
        }

#pragma unroll
    for (int o = 16; o; o >>= 1)
        pmax = fmaxf(pmax, __shfl_xor_sync(0xFFFFFFFFu, pmax, o));
    if ((tid & 31) == 0) red[tid >> 5] = pmax;
    __syncthreads();
    if (tid == 0) {
        float m = red[0];
#pragma unroll
        for (int w = 1; w < 8; w++) m = fmaxf(m, red[w]);
        atomicMax(&g_pmax, __float_as_uint(m));
    }
}

// ---------------------------------------------------------------------------
// Nyquist column f=256. grid = (NT/8, NC, NB), block 256.
// ---------------------------------------------------------------------------
__global__ void spec_nyq(const float* __restrict__ x,
                         const float* __restrict__ kre,
                         float* __restrict__ out) {
    const int tid = threadIdx.x, lane = tid & 31, w = tid >> 5;
    const int c = blockIdx.y, b = blockIdx.z;
    const int t = blockIdx.x * 8 + w;
    const float* xin = x + (size_t)(b * NC + c) * NL;
    const int gb = t * NHOP - PADL;
    float re = 0.f;
#pragma unroll 4
    for (int d = lane; d < ND; d += 32) {
        int g = gb + d;
        float xv = (g >= 0 && g < NL) ? xin[g] : 0.f;
        re = fmaf(xv, __ldg(&kre[d * NF + 256]), re);
    }
#pragma unroll
    for (int o = 16; o; o >>= 1) re += __shfl_xor_sync(0xFFFFFFFFu, re, o);
    __shared__ float pm[8];
    if (lane == 0) {
        float p = fmaxf(re * re, AMINF);
        out[(((size_t)b * NF + 256) * NT + t) * NC + c] =
            TEN_OVER_LOG2_10 * __log2f(p);
        pm[w] = p;
    }
    __syncthreads();
    if (tid == 0) {
        float m = pm[0];
#pragma unroll
        for (int i = 1; i < 8; i++) m = fmaxf(m, pm[i]);
        atomicMax(&g_pmax, __float_as_uint(m));
    }
}

// ---------------------------------------------------------------------------
__global__ void spec_fin(float* __restrict__ out, int n4) {
    int i = blockIdx.x * 256 + threadIdx.x;
    if (i >= n4) return;
    float lmax =
        TEN_OVER_LOG2_10 * __log2f(fmaxf(__uint_as_float(g_pmax), AMINF));
    float4 v = ((float4*)out)[i];
    v.x = fmaxf(v.x - lmax, -80.f);
    v.y = fmaxf(v.y - lmax, -80.f);
    v.z = fmaxf(v.z - lmax, -80.f);
    v.w = fmaxf(v.w - lmax, -80.f);
    ((float4*)out)[i] = v;
}

extern "C" void kernel_launch(void* const* d_in, const int* in_sizes, int n_in,
                              void* d_out, int out_size) {
    const float* x = (const float*)d_in[0];
    const float* kre = (const float*)d_in[1];
    const float* kim = (const float*)d_in[2];
    float* out = (float*)d_out;

    prep_kernel<<<256, 256>>>(kre, kim);

    dim3 gmain(NT / TT, NC, NB);
    spec_main<<<gmain, 256>>>(x, kre, out);

    dim3 gnyq(NT / 8, NC, NB);
    spec_nyq<<<gnyq, 256>>>(x, kre, out);

    int n4 = out_size / 4;
    spec_fin<<<(n4 + 255) / 256, 256>>>(out, n4);
}